// round 11
// baseline (speedup 1.0000x reference)
#include <cuda_runtime.h>
#include <cuda_fp16.h>
#include <cstdint>

#define DIM   1536
#define NH    24
#define HD    64
#define S_IMG 2048
#define T_TXT 512
#define LTOT  2560
#define GP    72

// ---------------- device scratch (no allocation allowed) -------------------
__device__ __half g_hshi[S_IMG * DIM], g_hslo[S_IMG * DIM];
__device__ __half g_ehi[T_TXT * DIM],  g_elo[T_TXT * DIM];
__device__ __half g_whi[8][DIM * DIM];
__device__ __half g_qhi[LTOT * DIM];
__device__ __half g_khi[LTOT * DIM];
__device__ __half g_vhi[LTOT * DIM];
__device__ __half g_ohi[LTOT * DIM], g_olo[LTOT * DIM];

// ---------------- base-ISA PTX helpers -------------------------------------
__device__ __forceinline__ uint32_t smem_u32(const void* p) {
    uint32_t a;
    asm("{ .reg .u64 t; cvta.to.shared.u64 t, %1; cvt.u32.u64 %0, t; }" : "=r"(a) : "l"(p));
    return a;
}
__device__ __forceinline__ void ldm_x4(uint32_t a, uint32_t* r) {
    asm volatile("ldmatrix.sync.aligned.m8n8.x4.shared.b16 {%0,%1,%2,%3}, [%4];"
        : "=r"(r[0]), "=r"(r[1]), "=r"(r[2]), "=r"(r[3]) : "r"(a));
}
__device__ __forceinline__ void ldm_x4t(uint32_t a, uint32_t* r) {
    asm volatile("ldmatrix.sync.aligned.m8n8.x4.trans.shared.b16 {%0,%1,%2,%3}, [%4];"
        : "=r"(r[0]), "=r"(r[1]), "=r"(r[2]), "=r"(r[3]) : "r"(a));
}
__device__ __forceinline__ void mma16816(float* c, const uint32_t* a, const uint32_t* b) {
    asm volatile(
        "mma.sync.aligned.m16n8k16.row.col.f32.f16.f16.f32 "
        "{%0,%1,%2,%3}, {%4,%5,%6,%7}, {%8,%9}, {%0,%1,%2,%3};"
        : "+f"(c[0]), "+f"(c[1]), "+f"(c[2]), "+f"(c[3])
        : "r"(a[0]), "r"(a[1]), "r"(a[2]), "r"(a[3]), "r"(b[0]), "r"(b[1]));
}
__device__ __forceinline__ void cpa16(uint32_t d, const void* g) {
    asm volatile("cp.async.cg.shared.global [%0], [%1], 16;" :: "r"(d), "l"(g));
}
#define CP_COMMIT() asm volatile("cp.async.commit_group;" ::: "memory")
#define CP_WAIT1()  asm volatile("cp.async.wait_group 1;" ::: "memory")
#define CP_WAIT0()  asm volatile("cp.async.wait_group 0;" ::: "memory")

// ---------------------------------------------------------------------------
// Converts
// ---------------------------------------------------------------------------
struct W8 { const float* s[8]; __half* d[8]; };

__global__ __launch_bounds__(256) void cvt_hi8(W8 w) {
    const float* s = w.s[blockIdx.y];
    __half* d = w.d[blockIdx.y];
    int i = (blockIdx.x * 256 + threadIdx.x) * 8;
    float4 a = *(const float4*)(s + i);
    float4 b = *(const float4*)(s + i + 4);
    __half2 h[4];
    h[0] = __floats2half2_rn(a.x, a.y);
    h[1] = __floats2half2_rn(a.z, a.w);
    h[2] = __floats2half2_rn(b.x, b.y);
    h[3] = __floats2half2_rn(b.z, b.w);
    *(uint4*)(d + i) = *(uint4*)h;
}

__global__ __launch_bounds__(256) void cvt_split(
    const float* __restrict__ s, __half* __restrict__ hi, __half* __restrict__ lo, int n)
{
    int i = (blockIdx.x * 256 + threadIdx.x) * 4;
    if (i >= n) return;
    float4 x = *(const float4*)(s + i);
    __half h0 = __float2half_rn(x.x), h1 = __float2half_rn(x.y);
    __half h2 = __float2half_rn(x.z), h3 = __float2half_rn(x.w);
    *(__half2*)(hi + i)     = __halves2half2(h0, h1);
    *(__half2*)(hi + i + 2) = __halves2half2(h2, h3);
    *(__half2*)(lo + i)     = __halves2half2(__float2half_rn(x.x - __half2float(h0)),
                                             __float2half_rn(x.y - __half2float(h1)));
    *(__half2*)(lo + i + 2) = __halves2half2(__float2half_rn(x.z - __half2float(h2)),
                                             __float2half_rn(x.w - __half2float(h3)));
}

// ---------------------------------------------------------------------------
// 2-term split GEMM: Y = (Xhi+Xlo) @ Whi^T + b (+ optional fused per-head LN)
// 128x128 tile, BK=64, cp.async double-buffered, 8 warps as 4(M)x2(N).
// B-fragments via ldmatrix.x4 (two n-tiles per LDSM).
// ---------------------------------------------------------------------------
struct GArg {
    const __half* Ahi[2]; const __half* Alo[2];
    const __half* Whi[2][3];
    const float* bias[2][3]; const float* gamma[2][3];
    __half* Ohi[3]; __half* Olo[3]; float* Of[3];
};

#define G_T (128 * GP)
#define G_STAGE (3 * G_T)
#define GEMM_SMEM (2 * G_STAGE * 2)

__global__ __launch_bounds__(256, 2) void gemm_split(GArg g)
{
    extern __shared__ __half sm[];
    const int tid = threadIdx.x, wid = tid >> 5, lane = tid & 31;
    const int part = blockIdx.y >= 16;
    const int arow0 = (part ? blockIdx.y - 16 : blockIdx.y) * 128;
    const int mOut = blockIdx.y * 128;
    const int z = blockIdx.z;
    const int n0 = blockIdx.x * 128;
    const __half* Ah = g.Ahi[part]; const __half* Al = g.Alo[part];
    const __half* Wh = g.Whi[part][z];
    const uint32_t sb0 = smem_u32(sm);

    auto load_stage = [&](int s, int k0) {
        uint32_t base = sb0 + (uint32_t)s * G_STAGE * 2;
        #pragma unroll
        for (int t = 0; t < 3; t++) {
            const __half* src = (t == 0) ? Ah : (t == 1) ? Al : Wh;
            const int rb = (t < 2) ? arow0 : n0;
            #pragma unroll
            for (int it = 0; it < 4; it++) {
                int idx = tid + it * 256;
                int row = idx >> 3, seg = idx & 7;
                cpa16(base + (uint32_t)(t * G_T + row * GP + seg * 8) * 2,
                      src + (size_t)(rb + row) * DIM + k0 + seg * 8);
            }
        }
        CP_COMMIT();
    };

    float C[2][8][4];
    #pragma unroll
    for (int a = 0; a < 2; a++)
        #pragma unroll
        for (int b = 0; b < 8; b++)
            #pragma unroll
            for (int c = 0; c < 4; c++) C[a][b][c] = 0.f;

    const int wm = (wid & 3) * 32;
    const int wn = (wid >> 2) * 64;

    load_stage(0, 0);
    for (int kc = 0; kc < 24; kc++) {
        if (kc + 1 < 24) { load_stage((kc + 1) & 1, (kc + 1) * 64); CP_WAIT1(); }
        else CP_WAIT0();
        __syncthreads();
        uint32_t sb = sb0 + (uint32_t)(kc & 1) * G_STAGE * 2;
        #pragma unroll
        for (int ks = 0; ks < 4; ks++) {
            uint32_t ah[2][4], al[2][4];
            #pragma unroll
            for (int mt = 0; mt < 2; mt++) {
                uint32_t a = sb + (uint32_t)((wm + mt * 16 + (lane & 15)) * GP
                                             + ks * 16 + (lane >> 4) * 8) * 2;
                ldm_x4(a, ah[mt]);
                ldm_x4(a + G_T * 2, al[mt]);
            }
            #pragma unroll
            for (int nt = 0; nt < 8; nt += 2) {
                uint32_t b4[4];
                uint32_t b = sb + (uint32_t)(2 * G_T
                             + (wn + nt * 8 + (lane & 7) + ((lane >> 4) << 3)) * GP
                             + ks * 16 + ((lane >> 3) & 1) * 8) * 2;
                ldm_x4(b, b4);
                #pragma unroll
                for (int mt = 0; mt < 2; mt++) {
                    mma16816(C[mt][nt], ah[mt], b4);
                    mma16816(C[mt][nt], al[mt], b4);
                    mma16816(C[mt][nt + 1], ah[mt], b4 + 2);
                    mma16816(C[mt][nt + 1], al[mt], b4 + 2);
                }
            }
        }
        __syncthreads();
    }

    const float* bias = g.bias[part][z];
    const float* gam  = g.gamma[part][z];
    __half* Oh = g.Ohi[z]; __half* Ol = g.Olo[z]; float* Of = g.Of[z];

    #pragma unroll
    for (int mt = 0; mt < 2; mt++)
        #pragma unroll
        for (int hf = 0; hf < 2; hf++) {
            const int row = mOut + wm + mt * 16 + (lane >> 2) + hf * 8;
            float v[16];
            #pragma unroll
            for (int nt = 0; nt < 8; nt++)
                #pragma unroll
                for (int j = 0; j < 2; j++)
                    v[nt * 2 + j] = C[mt][nt][hf * 2 + j]
                                  + bias[n0 + wn + nt * 8 + (lane & 3) * 2 + j];
            if (gam) {
                float s1 = 0.f, s2 = 0.f;
                #pragma unroll
                for (int c = 0; c < 16; c++) { s1 += v[c]; s2 += v[c] * v[c]; }
                s1 += __shfl_xor_sync(0xffffffffu, s1, 1);
                s2 += __shfl_xor_sync(0xffffffffu, s2, 1);
                s1 += __shfl_xor_sync(0xffffffffu, s1, 2);
                s2 += __shfl_xor_sync(0xffffffffu, s2, 2);
                float mean = s1 * (1.f / 64);
                float var = s2 * (1.f / 64) - mean * mean;
                float inv = rsqrtf(var + 1e-5f);
                #pragma unroll
                for (int nt = 0; nt < 8; nt++)
                    #pragma unroll
                    for (int j = 0; j < 2; j++) {
                        int c = nt * 2 + j;
                        v[c] = (v[c] - mean) * inv * gam[nt * 8 + (lane & 3) * 2 + j];
                    }
            }
            if (Oh) {
                #pragma unroll
                for (int nt = 0; nt < 8; nt++) {
                    int col = n0 + wn + nt * 8 + (lane & 3) * 2;
                    __half h0 = __float2half_rn(v[nt * 2]);
                    __half h1 = __float2half_rn(v[nt * 2 + 1]);
                    *(__half2*)(Oh + (size_t)row * DIM + col) = __halves2half2(h0, h1);
                    if (Ol)
                        *(__half2*)(Ol + (size_t)row * DIM + col) = __halves2half2(
                            __float2half_rn(v[nt * 2] - __half2float(h0)),
                            __float2half_rn(v[nt * 2 + 1] - __half2float(h1)));
                }
            } else {
                #pragma unroll
                for (int nt = 0; nt < 8; nt++) {
                    int col = n0 + wn + nt * 8 + (lane & 3) * 2;
                    *(float2*)(Of + (size_t)row * DIM + col) =
                        make_float2(v[nt * 2], v[nt * 2 + 1]);
                }
            }
        }
}

// ---------------------------------------------------------------------------
// mma flash attention. 8 warps x 16 q-rows (BQ=128), K-tiles of 64.
// S = Qh @ Kh ; O += P @ Vh (P fp16 from fp32). Stage tensors: Kh, Vh.
// B-fragments via ldmatrix.x4 (two tiles per LDSM).
// ---------------------------------------------------------------------------
#define A_T (64 * GP)
#define A_STAGE (2 * A_T)
#define ATT_SMEM (2 * A_STAGE * 2)

__global__ __launch_bounds__(256, 2) void attn_mma(
    const __half* __restrict__ Qh, const __half* __restrict__ Kh,
    const __half* __restrict__ Vh,
    __half* __restrict__ Oh, __half* __restrict__ Ol)
{
    extern __shared__ __half sm[];
    const int tid = threadIdx.x, wid = tid >> 5, lane = tid & 31;
    const int h = blockIdx.y;
    const int q0 = blockIdx.x * 128;
    const uint32_t sb0 = smem_u32(sm);
    const int hc = h * HD;

    // Stage Q (hi: 128 rows x 64 cols) into stage-0 region; read fragments.
    #pragma unroll
    for (int it = 0; it < 4; it++) {
        int idx = tid + it * 256;
        int row = idx >> 3, seg = idx & 7;
        cpa16(sb0 + (uint32_t)(row * GP + seg * 8) * 2,
              Qh + (size_t)(q0 + row) * DIM + hc + seg * 8);
    }
    CP_COMMIT(); CP_WAIT0();
    __syncthreads();

    uint32_t qh[4][4];
    #pragma unroll
    for (int ks = 0; ks < 4; ks++) {
        uint32_t a = sb0 + (uint32_t)((wid * 16 + (lane & 15)) * GP
                                      + ks * 16 + (lane >> 4) * 8) * 2;
        ldm_x4(a, qh[ks]);
    }
    __syncthreads();

    auto load_kv = [&](int s, int k0) {
        uint32_t base = sb0 + (uint32_t)s * A_STAGE * 2;
        #pragma unroll
        for (int t = 0; t < 2; t++) {
            const __half* src = (t == 0) ? Kh : Vh;
            #pragma unroll
            for (int it = 0; it < 2; it++) {
                int id2 = tid + it * 256;
                int row = id2 >> 3, seg = id2 & 7;
                cpa16(base + (uint32_t)(t * A_T + row * GP + seg * 8) * 2,
                      src + (size_t)(k0 + row) * DIM + hc + seg * 8);
            }
        }
        CP_COMMIT();
    };

    float m_i[2] = {-1e30f, -1e30f}, l_i[2] = {0.f, 0.f};
    float O[8][4];
    #pragma unroll
    for (int d = 0; d < 8; d++)
        #pragma unroll
        for (int c = 0; c < 4; c++) O[d][c] = 0.f;

    load_kv(0, 0);
    for (int kt = 0; kt < LTOT / 64; kt++) {
        if (kt + 1 < LTOT / 64) { load_kv((kt + 1) & 1, (kt + 1) * 64); CP_WAIT1(); }
        else CP_WAIT0();
        __syncthreads();
        uint32_t kb = sb0 + (uint32_t)(kt & 1) * A_STAGE * 2;

        float S[8][4];
        #pragma unroll
        for (int nt = 0; nt < 8; nt++)
            #pragma unroll
            for (int c = 0; c < 4; c++) S[nt][c] = 0.f;

        #pragma unroll
        for (int ks = 0; ks < 4; ks++)
            #pragma unroll
            for (int nt = 0; nt < 8; nt += 2) {
                uint32_t b4[4];
                uint32_t b = kb + (uint32_t)(
                    (nt * 8 + (lane & 7) + ((lane >> 4) << 3)) * GP
                    + ks * 16 + ((lane >> 3) & 1) * 8) * 2;
                ldm_x4(b, b4);
                mma16816(S[nt], qh[ks], b4);
                mma16816(S[nt + 1], qh[ks], b4 + 2);
            }

        uint32_t pa[4][4];
        #pragma unroll
        for (int hf = 0; hf < 2; hf++) {
            float tm = -1e30f;
            #pragma unroll
            for (int nt = 0; nt < 8; nt++)
                #pragma unroll
                for (int j = 0; j < 2; j++) {
                    S[nt][hf * 2 + j] *= 0.125f;
                    tm = fmaxf(tm, S[nt][hf * 2 + j]);
                }
            tm = fmaxf(tm, __shfl_xor_sync(0xffffffffu, tm, 1));
            tm = fmaxf(tm, __shfl_xor_sync(0xffffffffu, tm, 2));
            float mnew = fmaxf(m_i[hf], tm);
            float alpha = __expf(m_i[hf] - mnew);
            float rs = 0.f;
            #pragma unroll
            for (int nt = 0; nt < 8; nt++)
                #pragma unroll
                for (int j = 0; j < 2; j++) {
                    float p = __expf(S[nt][hf * 2 + j] - mnew);
                    S[nt][hf * 2 + j] = p;
                    rs += p;
                }
            rs += __shfl_xor_sync(0xffffffffu, rs, 1);
            rs += __shfl_xor_sync(0xffffffffu, rs, 2);
            l_i[hf] = l_i[hf] * alpha + rs;
            m_i[hf] = mnew;
            #pragma unroll
            for (int d = 0; d < 8; d++)
                #pragma unroll
                for (int j = 0; j < 2; j++) O[d][hf * 2 + j] *= alpha;
        }
        #pragma unroll
        for (int ks = 0; ks < 4; ks++) {
            __half2 p0 = __floats2half2_rn(S[2 * ks][0], S[2 * ks][1]);
            __half2 p1 = __floats2half2_rn(S[2 * ks][2], S[2 * ks][3]);
            __half2 p2 = __floats2half2_rn(S[2 * ks + 1][0], S[2 * ks + 1][1]);
            __half2 p3 = __floats2half2_rn(S[2 * ks + 1][2], S[2 * ks + 1][3]);
            pa[ks][0] = *(uint32_t*)&p0; pa[ks][1] = *(uint32_t*)&p1;
            pa[ks][2] = *(uint32_t*)&p2; pa[ks][3] = *(uint32_t*)&p3;
        }

        // O += P @ Vh (x4 trans: two d-tiles per LDSM)
        #pragma unroll
        for (int ks = 0; ks < 4; ks++)
            #pragma unroll
            for (int dt = 0; dt < 8; dt += 2) {
                uint32_t b4[4];
                uint32_t b = kb + (uint32_t)(A_T
                    + (ks * 16 + (lane & 15)) * GP
                    + (dt + (lane >> 4)) * 8) * 2;
                ldm_x4t(b, b4);
                mma16816(O[dt], pa[ks], b4);
                mma16816(O[dt + 1], pa[ks], b4 + 2);
            }
        __syncthreads();
    }

    #pragma unroll
    for (int hf = 0; hf < 2; hf++) {
        float inv = 1.f / l_i[hf];
        int row = q0 + wid * 16 + (lane >> 2) + hf * 8;
        #pragma unroll
        for (int dt = 0; dt < 8; dt++) {
            float v0 = O[dt][hf * 2] * inv, v1 = O[dt][hf * 2 + 1] * inv;
            int col = hc + dt * 8 + (lane & 3) * 2;
            __half h0 = __float2half_rn(v0), h1 = __float2half_rn(v1);
            *(__half2*)(Oh + (size_t)row * DIM + col) = __halves2half2(h0, h1);
            *(__half2*)(Ol + (size_t)row * DIM + col) = __halves2half2(
                __float2half_rn(v0 - __half2float(h0)),
                __float2half_rn(v1 - __half2float(h1)));
        }
    }
}

// ---------------------------------------------------------------------------
// Launch
// ---------------------------------------------------------------------------
extern "C" void kernel_launch(void* const* d_in, const int* in_sizes, int n_in,
                              void* d_out, int out_size)
{
    const float* hs  = (const float*)d_in[0];
    const float* ehs = (const float*)d_in[1];
    const float* Wq  = (const float*)d_in[2];
    const float* bq  = (const float*)d_in[3];
    const float* Wk  = (const float*)d_in[4];
    const float* bk  = (const float*)d_in[5];
    const float* Wv  = (const float*)d_in[6];
    const float* bv  = (const float*)d_in[7];
    const float* Waq = (const float*)d_in[8];
    const float* baq = (const float*)d_in[9];
    const float* Wak = (const float*)d_in[10];
    const float* bak = (const float*)d_in[11];
    const float* Wav = (const float*)d_in[12];
    const float* bav = (const float*)d_in[13];
    const float* Wo  = (const float*)d_in[14];
    const float* bo  = (const float*)d_in[15];
    const float* Wao = (const float*)d_in[16];
    const float* bao = (const float*)d_in[17];
    const float* gq  = (const float*)d_in[18];
    const float* gk  = (const float*)d_in[19];
    const float* gaq = (const float*)d_in[20];
    const float* gak = (const float*)d_in[21];
    float* out = (float*)d_out;

    __half *hshi, *hslo, *ehi, *elo, *whi;
    __half *qhi, *khi, *vhi, *ohi, *olo;
    cudaGetSymbolAddress((void**)&hshi, g_hshi);
    cudaGetSymbolAddress((void**)&hslo, g_hslo);
    cudaGetSymbolAddress((void**)&ehi, g_ehi);
    cudaGetSymbolAddress((void**)&elo, g_elo);
    cudaGetSymbolAddress((void**)&whi, g_whi);
    cudaGetSymbolAddress((void**)&qhi, g_qhi);
    cudaGetSymbolAddress((void**)&khi, g_khi);
    cudaGetSymbolAddress((void**)&vhi, g_vhi);
    cudaGetSymbolAddress((void**)&ohi, g_ohi);
    cudaGetSymbolAddress((void**)&olo, g_olo);

    const float* Ws[8] = {Wq, Wk, Wv, Waq, Wak, Wav, Wo, Wao};
    __half* wh[8];
    W8 wc;
    for (int i = 0; i < 8; i++) {
        wh[i] = whi + (size_t)i * DIM * DIM;
        wc.s[i] = Ws[i];
        wc.d[i] = wh[i];
    }
    cvt_hi8<<<dim3(DIM * DIM / 8 / 256, 8), 256>>>(wc);
    cvt_split<<<(S_IMG * DIM / 4 + 255) / 256, 256>>>(hs, hshi, hslo, S_IMG * DIM);
    cvt_split<<<(T_TXT * DIM / 4 + 255) / 256, 256>>>(ehs, ehi, elo, T_TXT * DIM);

    cudaFuncSetAttribute(gemm_split, cudaFuncAttributeMaxDynamicSharedMemorySize, GEMM_SMEM);
    cudaFuncSetAttribute(attn_mma, cudaFuncAttributeMaxDynamicSharedMemorySize, ATT_SMEM);

    // Projections: z = {q,k,v}; all hi-only outputs except none need lo now
    GArg pa;
    pa.Ahi[0] = hshi; pa.Alo[0] = hslo; pa.Ahi[1] = ehi; pa.Alo[1] = elo;
    pa.Whi[0][0] = wh[0]; pa.Whi[0][1] = wh[1]; pa.Whi[0][2] = wh[2];
    pa.Whi[1][0] = wh[3]; pa.Whi[1][1] = wh[4]; pa.Whi[1][2] = wh[5];
    pa.bias[0][0] = bq;  pa.bias[0][1] = bk;  pa.bias[0][2] = bv;
    pa.bias[1][0] = baq; pa.bias[1][1] = bak; pa.bias[1][2] = bav;
    pa.gamma[0][0] = gq;  pa.gamma[0][1] = gk;  pa.gamma[0][2] = nullptr;
    pa.gamma[1][0] = gaq; pa.gamma[1][1] = gak; pa.gamma[1][2] = nullptr;
    pa.Ohi[0] = qhi; pa.Ohi[1] = khi; pa.Ohi[2] = vhi;
    pa.Olo[0] = nullptr; pa.Olo[1] = nullptr; pa.Olo[2] = nullptr;
    pa.Of[0] = pa.Of[1] = pa.Of[2] = nullptr;
    gemm_split<<<dim3(DIM / 128, LTOT / 128, 3), 256, GEMM_SMEM>>>(pa);

    attn_mma<<<dim3(LTOT / 128, NH), 256, ATT_SMEM>>>(qhi, khi, vhi, ohi, olo);

    // Output projection straight into d_out (O kept hi+lo for input accuracy)
    GArg po;
    po.Ahi[0] = ohi; po.Alo[0] = olo;
    po.Ahi[1] = ohi + (size_t)S_IMG * DIM; po.Alo[1] = olo + (size_t)S_IMG * DIM;
    po.Whi[0][0] = wh[6]; po.Whi[1][0] = wh[7];
    po.Whi[0][1] = po.Whi[0][2] = po.Whi[1][1] = po.Whi[1][2] = nullptr;
    po.bias[0][0] = bo; po.bias[1][0] = bao;
    po.bias[0][1] = po.bias[0][2] = po.bias[1][1] = po.bias[1][2] = nullptr;
    po.gamma[0][0] = po.gamma[0][1] = po.gamma[0][2] = nullptr;
    po.gamma[1][0] = po.gamma[1][1] = po.gamma[1][2] = nullptr;
    po.Ohi[0] = po.Ohi[1] = po.Ohi[2] = nullptr;
    po.Olo[0] = po.Olo[1] = po.Olo[2] = nullptr;
    po.Of[0] = out; po.Of[1] = po.Of[2] = nullptr;
    gemm_split<<<dim3(DIM / 128, LTOT / 128, 1), 256, GEMM_SMEM>>>(po);
}

// round 12
// speedup vs baseline: 1.5190x; 1.5190x over previous
#include <cuda_runtime.h>
#include <cuda_fp16.h>
#include <cstdint>

#define DIM   1536
#define NH    24
#define HD    64
#define S_IMG 2048
#define T_TXT 512
#define LTOT  2560
#define GP    72

// ---------------- device scratch (no allocation allowed) -------------------
__device__ __half g_hshi[S_IMG * DIM], g_hslo[S_IMG * DIM];
__device__ __half g_ehi[T_TXT * DIM],  g_elo[T_TXT * DIM];
__device__ __half g_whi[8][DIM * DIM];
__device__ __half g_qhi[LTOT * DIM];
__device__ __half g_khi[LTOT * DIM];
__device__ __half g_vhi[LTOT * DIM];
__device__ __half g_ohi[LTOT * DIM], g_olo[LTOT * DIM];

// ---------------- base-ISA PTX helpers -------------------------------------
__device__ __forceinline__ uint32_t smem_u32(const void* p) {
    uint32_t a;
    asm("{ .reg .u64 t; cvta.to.shared.u64 t, %1; cvt.u32.u64 %0, t; }" : "=r"(a) : "l"(p));
    return a;
}
__device__ __forceinline__ void ldm_x4(uint32_t a, uint32_t* r) {
    asm volatile("ldmatrix.sync.aligned.m8n8.x4.shared.b16 {%0,%1,%2,%3}, [%4];"
        : "=r"(r[0]), "=r"(r[1]), "=r"(r[2]), "=r"(r[3]) : "r"(a));
}
__device__ __forceinline__ void ldm_x2(uint32_t a, uint32_t* r) {
    asm volatile("ldmatrix.sync.aligned.m8n8.x2.shared.b16 {%0,%1}, [%2];"
        : "=r"(r[0]), "=r"(r[1]) : "r"(a));
}
__device__ __forceinline__ void ldm_x2t(uint32_t a, uint32_t* r) {
    asm volatile("ldmatrix.sync.aligned.m8n8.x2.trans.shared.b16 {%0,%1}, [%2];"
        : "=r"(r[0]), "=r"(r[1]) : "r"(a));
}
__device__ __forceinline__ void mma16816(float* c, const uint32_t* a, const uint32_t* b) {
    asm volatile(
        "mma.sync.aligned.m16n8k16.row.col.f32.f16.f16.f32 "
        "{%0,%1,%2,%3}, {%4,%5,%6,%7}, {%8,%9}, {%0,%1,%2,%3};"
        : "+f"(c[0]), "+f"(c[1]), "+f"(c[2]), "+f"(c[3])
        : "r"(a[0]), "r"(a[1]), "r"(a[2]), "r"(a[3]), "r"(b[0]), "r"(b[1]));
}
__device__ __forceinline__ void cpa16(uint32_t d, const void* g) {
    asm volatile("cp.async.cg.shared.global [%0], [%1], 16;" :: "r"(d), "l"(g));
}
#define CP_COMMIT() asm volatile("cp.async.commit_group;" ::: "memory")
#define CP_WAIT1()  asm volatile("cp.async.wait_group 1;" ::: "memory")
#define CP_WAIT0()  asm volatile("cp.async.wait_group 0;" ::: "memory")

// ---------------------------------------------------------------------------
// Converts
// ---------------------------------------------------------------------------
struct W8 { const float* s[8]; __half* d[8]; };

__global__ __launch_bounds__(256) void cvt_hi8(W8 w) {
    const float* s = w.s[blockIdx.y];
    __half* d = w.d[blockIdx.y];
    int i = (blockIdx.x * 256 + threadIdx.x) * 8;
    float4 a = *(const float4*)(s + i);
    float4 b = *(const float4*)(s + i + 4);
    __half2 h[4];
    h[0] = __floats2half2_rn(a.x, a.y);
    h[1] = __floats2half2_rn(a.z, a.w);
    h[2] = __floats2half2_rn(b.x, b.y);
    h[3] = __floats2half2_rn(b.z, b.w);
    *(uint4*)(d + i) = *(uint4*)h;
}

__global__ __launch_bounds__(256) void cvt_split(
    const float* __restrict__ s, __half* __restrict__ hi, __half* __restrict__ lo, int n)
{
    int i = (blockIdx.x * 256 + threadIdx.x) * 4;
    if (i >= n) return;
    float4 x = *(const float4*)(s + i);
    __half h0 = __float2half_rn(x.x), h1 = __float2half_rn(x.y);
    __half h2 = __float2half_rn(x.z), h3 = __float2half_rn(x.w);
    *(__half2*)(hi + i)     = __halves2half2(h0, h1);
    *(__half2*)(hi + i + 2) = __halves2half2(h2, h3);
    *(__half2*)(lo + i)     = __halves2half2(__float2half_rn(x.x - __half2float(h0)),
                                             __float2half_rn(x.y - __half2float(h1)));
    *(__half2*)(lo + i + 2) = __halves2half2(__float2half_rn(x.z - __half2float(h2)),
                                             __float2half_rn(x.w - __half2float(h3)));
}

// ---------------------------------------------------------------------------
// 2-term split GEMM (R10-proven): Y = (Xhi+Xlo) @ Whi^T + b (+ fused LN)
// 128x128 tile, BK=64, cp.async double-buffered, 8 warps 4(M)x2(N), x2 B-loads.
// ---------------------------------------------------------------------------
struct GArg {
    const __half* Ahi[2]; const __half* Alo[2];
    const __half* Whi[2][3];
    const float* bias[2][3]; const float* gamma[2][3];
    __half* Ohi[3]; __half* Olo[3]; float* Of[3];
};

#define G_T (128 * GP)
#define G_STAGE (3 * G_T)
#define GEMM_SMEM (2 * G_STAGE * 2)

__global__ __launch_bounds__(256, 2) void gemm_split(GArg g)
{
    extern __shared__ __half sm[];
    const int tid = threadIdx.x, wid = tid >> 5, lane = tid & 31;
    const int part = blockIdx.y >= 16;
    const int arow0 = (part ? blockIdx.y - 16 : blockIdx.y) * 128;
    const int mOut = blockIdx.y * 128;
    const int z = blockIdx.z;
    const int n0 = blockIdx.x * 128;
    const __half* Ah = g.Ahi[part]; const __half* Al = g.Alo[part];
    const __half* Wh = g.Whi[part][z];
    const uint32_t sb0 = smem_u32(sm);

    auto load_stage = [&](int s, int k0) {
        uint32_t base = sb0 + (uint32_t)s * G_STAGE * 2;
        #pragma unroll
        for (int t = 0; t < 3; t++) {
            const __half* src = (t == 0) ? Ah : (t == 1) ? Al : Wh;
            const int rb = (t < 2) ? arow0 : n0;
            #pragma unroll
            for (int it = 0; it < 4; it++) {
                int idx = tid + it * 256;
                int row = idx >> 3, seg = idx & 7;
                cpa16(base + (uint32_t)(t * G_T + row * GP + seg * 8) * 2,
                      src + (size_t)(rb + row) * DIM + k0 + seg * 8);
            }
        }
        CP_COMMIT();
    };

    float C[2][8][4];
    #pragma unroll
    for (int a = 0; a < 2; a++)
        #pragma unroll
        for (int b = 0; b < 8; b++)
            #pragma unroll
            for (int c = 0; c < 4; c++) C[a][b][c] = 0.f;

    const int wm = (wid & 3) * 32;
    const int wn = (wid >> 2) * 64;

    load_stage(0, 0);
    for (int kc = 0; kc < 24; kc++) {
        if (kc + 1 < 24) { load_stage((kc + 1) & 1, (kc + 1) * 64); CP_WAIT1(); }
        else CP_WAIT0();
        __syncthreads();
        uint32_t sb = sb0 + (uint32_t)(kc & 1) * G_STAGE * 2;
        #pragma unroll
        for (int ks = 0; ks < 4; ks++) {
            uint32_t ah[2][4], al[2][4];
            #pragma unroll
            for (int mt = 0; mt < 2; mt++) {
                uint32_t a = sb + (uint32_t)((wm + mt * 16 + (lane & 15)) * GP
                                             + ks * 16 + (lane >> 4) * 8) * 2;
                ldm_x4(a, ah[mt]);
                ldm_x4(a + G_T * 2, al[mt]);
            }
            #pragma unroll
            for (int nt = 0; nt < 8; nt++) {
                uint32_t bh[2];
                uint32_t b = sb + (uint32_t)(2 * G_T + (wn + nt * 8 + (lane & 7)) * GP
                                             + ks * 16 + ((lane >> 3) & 1) * 8) * 2;
                ldm_x2(b, bh);
                #pragma unroll
                for (int mt = 0; mt < 2; mt++) {
                    mma16816(C[mt][nt], ah[mt], bh);
                    mma16816(C[mt][nt], al[mt], bh);
                }
            }
        }
        __syncthreads();
    }

    const float* bias = g.bias[part][z];
    const float* gam  = g.gamma[part][z];
    __half* Oh = g.Ohi[z]; __half* Ol = g.Olo[z]; float* Of = g.Of[z];

    #pragma unroll
    for (int mt = 0; mt < 2; mt++)
        #pragma unroll
        for (int hf = 0; hf < 2; hf++) {
            const int row = mOut + wm + mt * 16 + (lane >> 2) + hf * 8;
            float v[16];
            #pragma unroll
            for (int nt = 0; nt < 8; nt++)
                #pragma unroll
                for (int j = 0; j < 2; j++)
                    v[nt * 2 + j] = C[mt][nt][hf * 2 + j]
                                  + bias[n0 + wn + nt * 8 + (lane & 3) * 2 + j];
            if (gam) {
                float s1 = 0.f, s2 = 0.f;
                #pragma unroll
                for (int c = 0; c < 16; c++) { s1 += v[c]; s2 += v[c] * v[c]; }
                s1 += __shfl_xor_sync(0xffffffffu, s1, 1);
                s2 += __shfl_xor_sync(0xffffffffu, s2, 1);
                s1 += __shfl_xor_sync(0xffffffffu, s1, 2);
                s2 += __shfl_xor_sync(0xffffffffu, s2, 2);
                float mean = s1 * (1.f / 64);
                float var = s2 * (1.f / 64) - mean * mean;
                float inv = rsqrtf(var + 1e-5f);
                #pragma unroll
                for (int nt = 0; nt < 8; nt++)
                    #pragma unroll
                    for (int j = 0; j < 2; j++) {
                        int c = nt * 2 + j;
                        v[c] = (v[c] - mean) * inv * gam[nt * 8 + (lane & 3) * 2 + j];
                    }
            }
            if (Oh) {
                #pragma unroll
                for (int nt = 0; nt < 8; nt++) {
                    int col = n0 + wn + nt * 8 + (lane & 3) * 2;
                    __half h0 = __float2half_rn(v[nt * 2]);
                    __half h1 = __float2half_rn(v[nt * 2 + 1]);
                    *(__half2*)(Oh + (size_t)row * DIM + col) = __halves2half2(h0, h1);
                    if (Ol)
                        *(__half2*)(Ol + (size_t)row * DIM + col) = __halves2half2(
                            __float2half_rn(v[nt * 2] - __half2float(h0)),
                            __float2half_rn(v[nt * 2 + 1] - __half2float(h1)));
                }
            } else {
                #pragma unroll
                for (int nt = 0; nt < 8; nt++) {
                    int col = n0 + wn + nt * 8 + (lane & 3) * 2;
                    *(float2*)(Of + (size_t)row * DIM + col) =
                        make_float2(v[nt * 2], v[nt * 2 + 1]);
                }
            }
        }
}

// ---------------------------------------------------------------------------
// mma flash attention. 8 warps x 16 q-rows (BQ=128), K-tiles of 64.
// S = Qh @ Kh ; O += P @ Vh. Stage tensors: Kh, Vh. x2/x2t loads (R10 pattern).
// ---------------------------------------------------------------------------
#define A_T (64 * GP)
#define A_STAGE (2 * A_T)
#define ATT_SMEM (2 * A_STAGE * 2)

__global__ __launch_bounds__(256, 2) void attn_mma(
    const __half* __restrict__ Qh, const __half* __restrict__ Kh,
    const __half* __restrict__ Vh,
    __half* __restrict__ Oh, __half* __restrict__ Ol)
{
    extern __shared__ __half sm[];
    const int tid = threadIdx.x, wid = tid >> 5, lane = tid & 31;
    const int h = blockIdx.y;
    const int q0 = blockIdx.x * 128;
    const uint32_t sb0 = smem_u32(sm);
    const int hc = h * HD;

    // Stage Q (hi: 128 rows x 64 cols); read fragments.
    #pragma unroll
    for (int it = 0; it < 4; it++) {
        int idx = tid + it * 256;
        int row = idx >> 3, seg = idx & 7;
        cpa16(sb0 + (uint32_t)(row * GP + seg * 8) * 2,
              Qh + (size_t)(q0 + row) * DIM + hc + seg * 8);
    }
    CP_COMMIT(); CP_WAIT0();
    __syncthreads();

    uint32_t qh[4][4];
    #pragma unroll
    for (int ks = 0; ks < 4; ks++) {
        uint32_t a = sb0 + (uint32_t)((wid * 16 + (lane & 15)) * GP
                                      + ks * 16 + (lane >> 4) * 8) * 2;
        ldm_x4(a, qh[ks]);
    }
    __syncthreads();

    auto load_kv = [&](int s, int k0) {
        uint32_t base = sb0 + (uint32_t)s * A_STAGE * 2;
        #pragma unroll
        for (int t = 0; t < 2; t++) {
            const __half* src = (t == 0) ? Kh : Vh;
            #pragma unroll
            for (int it = 0; it < 2; it++) {
                int id2 = tid + it * 256;
                int row = id2 >> 3, seg = id2 & 7;
                cpa16(base + (uint32_t)(t * A_T + row * GP + seg * 8) * 2,
                      src + (size_t)(k0 + row) * DIM + hc + seg * 8);
            }
        }
        CP_COMMIT();
    };

    float m_i[2] = {-1e30f, -1e30f}, l_i[2] = {0.f, 0.f};
    float O[8][4];
    #pragma unroll
    for (int d = 0; d < 8; d++)
        #pragma unroll
        for (int c = 0; c < 4; c++) O[d][c] = 0.f;

    load_kv(0, 0);
    for (int kt = 0; kt < LTOT / 64; kt++) {
        if (kt + 1 < LTOT / 64) { load_kv((kt + 1) & 1, (kt + 1) * 64); CP_WAIT1(); }
        else CP_WAIT0();
        __syncthreads();
        uint32_t kb = sb0 + (uint32_t)(kt & 1) * A_STAGE * 2;

        float S[8][4];
        #pragma unroll
        for (int nt = 0; nt < 8; nt++)
            #pragma unroll
            for (int c = 0; c < 4; c++) S[nt][c] = 0.f;

        #pragma unroll
        for (int ks = 0; ks < 4; ks++)
            #pragma unroll
            for (int nt = 0; nt < 8; nt++) {
                uint32_t bh[2];
                uint32_t b = kb + (uint32_t)((nt * 8 + (lane & 7)) * GP
                                             + ks * 16 + ((lane >> 3) & 1) * 8) * 2;
                ldm_x2(b, bh);
                mma16816(S[nt], qh[ks], bh);
            }

        uint32_t pa[4][4];
        #pragma unroll
        for (int hf = 0; hf < 2; hf++) {
            float tm = -1e30f;
            #pragma unroll
            for (int nt = 0; nt < 8; nt++)
                #pragma unroll
                for (int j = 0; j < 2; j++) {
                    S[nt][hf * 2 + j] *= 0.125f;
                    tm = fmaxf(tm, S[nt][hf * 2 + j]);
                }
            tm = fmaxf(tm, __shfl_xor_sync(0xffffffffu, tm, 1));
            tm = fmaxf(tm, __shfl_xor_sync(0xffffffffu, tm, 2));
            float mnew = fmaxf(m_i[hf], tm);
            float alpha = __expf(m_i[hf] - mnew);
            float rs = 0.f;
            #pragma unroll
            for (int nt = 0; nt < 8; nt++)
                #pragma unroll
                for (int j = 0; j < 2; j++) {
                    float p = __expf(S[nt][hf * 2 + j] - mnew);
                    S[nt][hf * 2 + j] = p;
                    rs += p;
                }
            rs += __shfl_xor_sync(0xffffffffu, rs, 1);
            rs += __shfl_xor_sync(0xffffffffu, rs, 2);
            l_i[hf] = l_i[hf] * alpha + rs;
            m_i[hf] = mnew;
            #pragma unroll
            for (int d = 0; d < 8; d++)
                #pragma unroll
                for (int j = 0; j < 2; j++) O[d][hf * 2 + j] *= alpha;
        }
        #pragma unroll
        for (int ks = 0; ks < 4; ks++) {
            __half2 p0 = __floats2half2_rn(S[2 * ks][0], S[2 * ks][1]);
            __half2 p1 = __floats2half2_rn(S[2 * ks][2], S[2 * ks][3]);
            __half2 p2 = __floats2half2_rn(S[2 * ks + 1][0], S[2 * ks + 1][1]);
            __half2 p3 = __floats2half2_rn(S[2 * ks + 1][2], S[2 * ks + 1][3]);
            pa[ks][0] = *(uint32_t*)&p0; pa[ks][1] = *(uint32_t*)&p1;
            pa[ks][2] = *(uint32_t*)&p2; pa[ks][3] = *(uint32_t*)&p3;
        }

        // O += P @ Vh (x2 trans per d-tile, R10 pattern)
        #pragma unroll
        for (int ks = 0; ks < 4; ks++)
            #pragma unroll
            for (int dt = 0; dt < 8; dt++) {
                uint32_t bh[2];
                uint32_t b = kb + (uint32_t)(A_T + (ks * 16 + (lane & 15)) * GP
                                             + dt * 8) * 2;
                ldm_x2t(b, bh);
                mma16816(O[dt], pa[ks], bh);
            }
        __syncthreads();
    }

    #pragma unroll
    for (int hf = 0; hf < 2; hf++) {
        float inv = 1.f / l_i[hf];
        int row = q0 + wid * 16 + (lane >> 2) + hf * 8;
        #pragma unroll
        for (int dt = 0; dt < 8; dt++) {
            float v0 = O[dt][hf * 2] * inv, v1 = O[dt][hf * 2 + 1] * inv;
            int col = hc + dt * 8 + (lane & 3) * 2;
            __half h0 = __float2half_rn(v0), h1 = __float2half_rn(v1);
            *(__half2*)(Oh + (size_t)row * DIM + col) = __halves2half2(h0, h1);
            *(__half2*)(Ol + (size_t)row * DIM + col) = __halves2half2(
                __float2half_rn(v0 - __half2float(h0)),
                __float2half_rn(v1 - __half2float(h1)));
        }
    }
}

// ---------------------------------------------------------------------------
// Launch
// ---------------------------------------------------------------------------
extern "C" void kernel_launch(void* const* d_in, const int* in_sizes, int n_in,
                              void* d_out, int out_size)
{
    const float* hs  = (const float*)d_in[0];
    const float* ehs = (const float*)d_in[1];
    const float* Wq  = (const float*)d_in[2];
    const float* bq  = (const float*)d_in[3];
    const float* Wk  = (const float*)d_in[4];
    const float* bk  = (const float*)d_in[5];
    const float* Wv  = (const float*)d_in[6];
    const float* bv  = (const float*)d_in[7];
    const float* Waq = (const float*)d_in[8];
    const float* baq = (const float*)d_in[9];
    const float* Wak = (const float*)d_in[10];
    const float* bak = (const float*)d_in[11];
    const float* Wav = (const float*)d_in[12];
    const float* bav = (const float*)d_in[13];
    const float* Wo  = (const float*)d_in[14];
    const float* bo  = (const float*)d_in[15];
    const float* Wao = (const float*)d_in[16];
    const float* bao = (const float*)d_in[17];
    const float* gq  = (const float*)d_in[18];
    const float* gk  = (const float*)d_in[19];
    const float* gaq = (const float*)d_in[20];
    const float* gak = (const float*)d_in[21];
    float* out = (float*)d_out;

    __half *hshi, *hslo, *ehi, *elo, *whi;
    __half *qhi, *khi, *vhi, *ohi, *olo;
    cudaGetSymbolAddress((void**)&hshi, g_hshi);
    cudaGetSymbolAddress((void**)&hslo, g_hslo);
    cudaGetSymbolAddress((void**)&ehi, g_ehi);
    cudaGetSymbolAddress((void**)&elo, g_elo);
    cudaGetSymbolAddress((void**)&whi, g_whi);
    cudaGetSymbolAddress((void**)&qhi, g_qhi);
    cudaGetSymbolAddress((void**)&khi, g_khi);
    cudaGetSymbolAddress((void**)&vhi, g_vhi);
    cudaGetSymbolAddress((void**)&ohi, g_ohi);
    cudaGetSymbolAddress((void**)&olo, g_olo);

    const float* Ws[8] = {Wq, Wk, Wv, Waq, Wak, Wav, Wo, Wao};
    __half* wh[8];
    W8 wc;
    for (int i = 0; i < 8; i++) {
        wh[i] = whi + (size_t)i * DIM * DIM;
        wc.s[i] = Ws[i];
        wc.d[i] = wh[i];
    }
    cvt_hi8<<<dim3(DIM * DIM / 8 / 256, 8), 256>>>(wc);
    cvt_split<<<(S_IMG * DIM / 4 + 255) / 256, 256>>>(hs, hshi, hslo, S_IMG * DIM);
    cvt_split<<<(T_TXT * DIM / 4 + 255) / 256, 256>>>(ehs, ehi, elo, T_TXT * DIM);

    cudaFuncSetAttribute(gemm_split, cudaFuncAttributeMaxDynamicSharedMemorySize, GEMM_SMEM);
    cudaFuncSetAttribute(attn_mma, cudaFuncAttributeMaxDynamicSharedMemorySize, ATT_SMEM);

    // Projections: z = {q,k,v}; hi-only outputs
    GArg pa;
    pa.Ahi[0] = hshi; pa.Alo[0] = hslo; pa.Ahi[1] = ehi; pa.Alo[1] = elo;
    pa.Whi[0][0] = wh[0]; pa.Whi[0][1] = wh[1]; pa.Whi[0][2] = wh[2];
    pa.Whi[1][0] = wh[3]; pa.Whi[1][1] = wh[4]; pa.Whi[1][2] = wh[5];
    pa.bias[0][0] = bq;  pa.bias[0][1] = bk;  pa.bias[0][2] = bv;
    pa.bias[1][0] = baq; pa.bias[1][1] = bak; pa.bias[1][2] = bav;
    pa.gamma[0][0] = gq;  pa.gamma[0][1] = gk;  pa.gamma[0][2] = nullptr;
    pa.gamma[1][0] = gaq; pa.gamma[1][1] = gak; pa.gamma[1][2] = nullptr;
    pa.Ohi[0] = qhi; pa.Ohi[1] = khi; pa.Ohi[2] = vhi;
    pa.Olo[0] = nullptr; pa.Olo[1] = nullptr; pa.Olo[2] = nullptr;
    pa.Of[0] = pa.Of[1] = pa.Of[2] = nullptr;
    gemm_split<<<dim3(DIM / 128, LTOT / 128, 3), 256, GEMM_SMEM>>>(pa);

    attn_mma<<<dim3(LTOT / 128, NH), 256, ATT_SMEM>>>(qhi, khi, vhi, ohi, olo);

    // Output projection straight into d_out (O kept hi+lo)
    GArg po;
    po.Ahi[0] = ohi; po.Alo[0] = olo;
    po.Ahi[1] = ohi + (size_t)S_IMG * DIM; po.Alo[1] = olo + (size_t)S_IMG * DIM;
    po.Whi[0][0] = wh[6]; po.Whi[1][0] = wh[7];
    po.Whi[0][1] = po.Whi[0][2] = po.Whi[1][1] = po.Whi[1][2] = nullptr;
    po.bias[0][0] = bo; po.bias[1][0] = bao;
    po.bias[0][1] = po.bias[0][2] = po.bias[1][1] = po.bias[1][2] = nullptr;
    po.gamma[0][0] = po.gamma[0][1] = po.gamma[0][2] = nullptr;
    po.gamma[1][0] = po.gamma[1][1] = po.gamma[1][2] = nullptr;
    po.Ohi[0] = po.Ohi[1] = po.Ohi[2] = nullptr;
    po.Olo[0] = po.Olo[1] = po.Olo[2] = nullptr;
    po.Of[0] = out; po.Of[1] = po.Of[2] = nullptr;
    gemm_split<<<dim3(DIM / 128, LTOT / 128, 1), 256, GEMM_SMEM>>>(po);
}

// round 14
// speedup vs baseline: 1.8073x; 1.1899x over previous
#include <cuda_runtime.h>
#include <cuda_fp16.h>
#include <cstdint>

#define DIM   1536
#define NH    24
#define HD    64
#define S_IMG 2048
#define T_TXT 512
#define LTOT  2560
#define GP    72

// ---------------- device scratch (no allocation allowed) -------------------
__device__ __half g_hshi[S_IMG * DIM];
__device__ __half g_ehi[T_TXT * DIM];
__device__ __half g_whi[8][DIM * DIM];
__device__ __half g_qhi[LTOT * DIM];
__device__ __half g_khi[LTOT * DIM];
__device__ __half g_vhi[LTOT * DIM];
__device__ __half g_ohi[LTOT * DIM], g_olo[LTOT * DIM];

// ---------------- base-ISA PTX helpers -------------------------------------
__device__ __forceinline__ uint32_t smem_u32(const void* p) {
    uint32_t a;
    asm("{ .reg .u64 t; cvta.to.shared.u64 t, %1; cvt.u32.u64 %0, t; }" : "=r"(a) : "l"(p));
    return a;
}
__device__ __forceinline__ void ldm_x4(uint32_t a, uint32_t* r) {
    asm volatile("ldmatrix.sync.aligned.m8n8.x4.shared.b16 {%0,%1,%2,%3}, [%4];"
        : "=r"(r[0]), "=r"(r[1]), "=r"(r[2]), "=r"(r[3]) : "r"(a));
}
__device__ __forceinline__ void ldm_x2(uint32_t a, uint32_t* r) {
    asm volatile("ldmatrix.sync.aligned.m8n8.x2.shared.b16 {%0,%1}, [%2];"
        : "=r"(r[0]), "=r"(r[1]) : "r"(a));
}
__device__ __forceinline__ void ldm_x2t(uint32_t a, uint32_t* r) {
    asm volatile("ldmatrix.sync.aligned.m8n8.x2.trans.shared.b16 {%0,%1}, [%2];"
        : "=r"(r[0]), "=r"(r[1]) : "r"(a));
}
__device__ __forceinline__ void mma16816(float* c, const uint32_t* a, const uint32_t* b) {
    asm volatile(
        "mma.sync.aligned.m16n8k16.row.col.f32.f16.f16.f32 "
        "{%0,%1,%2,%3}, {%4,%5,%6,%7}, {%8,%9}, {%0,%1,%2,%3};"
        : "+f"(c[0]), "+f"(c[1]), "+f"(c[2]), "+f"(c[3])
        : "r"(a[0]), "r"(a[1]), "r"(a[2]), "r"(a[3]), "r"(b[0]), "r"(b[1]));
}
__device__ __forceinline__ void cpa16(uint32_t d, const void* g) {
    asm volatile("cp.async.cg.shared.global [%0], [%1], 16;" :: "r"(d), "l"(g));
}
#define CP_COMMIT() asm volatile("cp.async.commit_group;" ::: "memory")
#define CP_WAIT1()  asm volatile("cp.async.wait_group 1;" ::: "memory")
#define CP_WAIT0()  asm volatile("cp.async.wait_group 0;" ::: "memory")

// ---------------------------------------------------------------------------
// Converts
// ---------------------------------------------------------------------------
struct W8 { const float* s[8]; __half* d[8]; };

__global__ __launch_bounds__(256) void cvt_hi8(W8 w) {
    const float* s = w.s[blockIdx.y];
    __half* d = w.d[blockIdx.y];
    int i = (blockIdx.x * 256 + threadIdx.x) * 8;
    float4 a = *(const float4*)(s + i);
    float4 b = *(const float4*)(s + i + 4);
    __half2 h[4];
    h[0] = __floats2half2_rn(a.x, a.y);
    h[1] = __floats2half2_rn(a.z, a.w);
    h[2] = __floats2half2_rn(b.x, b.y);
    h[3] = __floats2half2_rn(b.z, b.w);
    *(uint4*)(d + i) = *(uint4*)h;
}

__global__ __launch_bounds__(256) void cvt_hi(
    const float* __restrict__ s, __half* __restrict__ d, int n)
{
    int i = (blockIdx.x * 256 + threadIdx.x) * 8;
    if (i >= n) return;
    float4 a = *(const float4*)(s + i);
    float4 b = *(const float4*)(s + i + 4);
    __half2 h[4];
    h[0] = __floats2half2_rn(a.x, a.y);
    h[1] = __floats2half2_rn(a.z, a.w);
    h[2] = __floats2half2_rn(b.x, b.y);
    h[3] = __floats2half2_rn(b.z, b.w);
    *(uint4*)(d + i) = *(uint4*)h;
}

// ---------------------------------------------------------------------------
// GEMM: Y = A @ Wh^T + b (+ optional fused per-head LN).
// LO=true: A = Ahi + Alo (2-term, 3 staged tensors). LO=false: A = Ahi only.
// 128x128 tile, BK=64, cp.async double-buffered, 8 warps 4(M)x2(N), x2 B-loads.
// ---------------------------------------------------------------------------
struct GArg {
    const __half* Ahi[2]; const __half* Alo[2];
    const __half* Whi[2][3];
    const float* bias[2][3]; const float* gamma[2][3];
    __half* Ohi[3]; __half* Olo[3]; float* Of[3];
};

#define G_T (128 * GP)
#define GEMM_SMEM_LO (2 * 3 * G_T * 2)
#define GEMM_SMEM_HI (2 * 2 * G_T * 2)

template <bool LO>
__global__ __launch_bounds__(256, 2) void gemm_split(GArg g)
{
    constexpr int NT = LO ? 3 : 2;           // staged tensors
    constexpr uint32_t GS = NT * G_T;        // halves per stage
    constexpr uint32_t BOFF = (NT - 1) * G_T;
    extern __shared__ __half sm[];
    const int tid = threadIdx.x, wid = tid >> 5, lane = tid & 31;
    const int part = blockIdx.y >= 16;
    const int arow0 = (part ? blockIdx.y - 16 : blockIdx.y) * 128;
    const int mOut = blockIdx.y * 128;
    const int z = blockIdx.z;
    const int n0 = blockIdx.x * 128;
    const __half* Ah = g.Ahi[part]; const __half* Al = g.Alo[part];
    const __half* Wh = g.Whi[part][z];
    const uint32_t sb0 = smem_u32(sm);

    auto load_stage = [&](int s, int k0) {
        uint32_t base = sb0 + (uint32_t)s * GS * 2;
        #pragma unroll
        for (int t = 0; t < NT; t++) {
            const __half* src = (t == NT - 1) ? Wh : (t == 0 ? Ah : Al);
            const int rb = (t == NT - 1) ? n0 : arow0;
            #pragma unroll
            for (int it = 0; it < 4; it++) {
                int idx = tid + it * 256;
                int row = idx >> 3, seg = idx & 7;
                cpa16(base + (uint32_t)(t * G_T + row * GP + seg * 8) * 2,
                      src + (size_t)(rb + row) * DIM + k0 + seg * 8);
            }
        }
        CP_COMMIT();
    };

    float C[2][8][4];
    #pragma unroll
    for (int a = 0; a < 2; a++)
        #pragma unroll
        for (int b = 0; b < 8; b++)
            #pragma unroll
            for (int c = 0; c < 4; c++) C[a][b][c] = 0.f;

    const int wm = (wid & 3) * 32;
    const int wn = (wid >> 2) * 64;

    load_stage(0, 0);
    for (int kc = 0; kc < 24; kc++) {
        if (kc + 1 < 24) { load_stage((kc + 1) & 1, (kc + 1) * 64); CP_WAIT1(); }
        else CP_WAIT0();
        __syncthreads();
        uint32_t sb = sb0 + (uint32_t)(kc & 1) * GS * 2;
        #pragma unroll
        for (int ks = 0; ks < 4; ks++) {
            uint32_t ah[2][4], al[2][4];
            #pragma unroll
            for (int mt = 0; mt < 2; mt++) {
                uint32_t a = sb + (uint32_t)((wm + mt * 16 + (lane & 15)) * GP
                                             + ks * 16 + (lane >> 4) * 8) * 2;
                ldm_x4(a, ah[mt]);
                if (LO) ldm_x4(a + G_T * 2, al[mt]);
            }
            #pragma unroll
            for (int nt = 0; nt < 8; nt++) {
                uint32_t bh[2];
                uint32_t b = sb + (uint32_t)(BOFF + (wn + nt * 8 + (lane & 7)) * GP
                                             + ks * 16 + ((lane >> 3) & 1) * 8) * 2;
                ldm_x2(b, bh);
                #pragma unroll
                for (int mt = 0; mt < 2; mt++) {
                    mma16816(C[mt][nt], ah[mt], bh);
                    if (LO) mma16816(C[mt][nt], al[mt], bh);
                }
            }
        }
        __syncthreads();
    }

    const float* bias = g.bias[part][z];
    const float* gam  = g.gamma[part][z];
    __half* Oh = g.Ohi[z]; __half* Ol = g.Olo[z]; float* Of = g.Of[z];

    #pragma unroll
    for (int mt = 0; mt < 2; mt++)
        #pragma unroll
        for (int hf = 0; hf < 2; hf++) {
            const int row = mOut + wm + mt * 16 + (lane >> 2) + hf * 8;
            float v[16];
            #pragma unroll
            for (int nt = 0; nt < 8; nt++)
                #pragma unroll
                for (int j = 0; j < 2; j++)
                    v[nt * 2 + j] = C[mt][nt][hf * 2 + j]
                                  + bias[n0 + wn + nt * 8 + (lane & 3) * 2 + j];
            if (gam) {
                float s1 = 0.f, s2 = 0.f;
                #pragma unroll
                for (int c = 0; c < 16; c++) { s1 += v[c]; s2 += v[c] * v[c]; }
                s1 += __shfl_xor_sync(0xffffffffu, s1, 1);
                s2 += __shfl_xor_sync(0xffffffffu, s2, 1);
                s1 += __shfl_xor_sync(0xffffffffu, s1, 2);
                s2 += __shfl_xor_sync(0xffffffffu, s2, 2);
                float mean = s1 * (1.f / 64);
                float var = s2 * (1.f / 64) - mean * mean;
                float inv = rsqrtf(var + 1e-5f);
                #pragma unroll
                for (int nt = 0; nt < 8; nt++)
                    #pragma unroll
                    for (int j = 0; j < 2; j++) {
                        int c = nt * 2 + j;
                        v[c] = (v[c] - mean) * inv * gam[nt * 8 + (lane & 3) * 2 + j];
                    }
            }
            if (Oh) {
                #pragma unroll
                for (int nt = 0; nt < 8; nt++) {
                    int col = n0 + wn + nt * 8 + (lane & 3) * 2;
                    __half h0 = __float2half_rn(v[nt * 2]);
                    __half h1 = __float2half_rn(v[nt * 2 + 1]);
                    *(__half2*)(Oh + (size_t)row * DIM + col) = __halves2half2(h0, h1);
                    if (Ol)
                        *(__half2*)(Ol + (size_t)row * DIM + col) = __halves2half2(
                            __float2half_rn(v[nt * 2] - __half2float(h0)),
                            __float2half_rn(v[nt * 2 + 1] - __half2float(h1)));
                }
            } else {
                #pragma unroll
                for (int nt = 0; nt < 8; nt++) {
                    int col = n0 + wn + nt * 8 + (lane & 3) * 2;
                    *(float2*)(Of + (size_t)row * DIM + col) =
                        make_float2(v[nt * 2], v[nt * 2 + 1]);
                }
            }
        }
}

// ---------------------------------------------------------------------------
// mma flash attention (R12-proven). 8 warps x 16 q-rows, K-tiles of 64.
// S = Qh @ Kh ; O += P @ Vh. x2/x2t loads.
// ---------------------------------------------------------------------------
#define A_T (64 * GP)
#define A_STAGE (2 * A_T)
#define ATT_SMEM (2 * A_STAGE * 2)

__global__ __launch_bounds__(256, 2) void attn_mma(
    const __half* __restrict__ Qh, const __half* __restrict__ Kh,
    const __half* __restrict__ Vh,
    __half* __restrict__ Oh, __half* __restrict__ Ol)
{
    extern __shared__ __half sm[];
    const int tid = threadIdx.x, wid = tid >> 5, lane = tid & 31;
    const int h = blockIdx.y;
    const int q0 = blockIdx.x * 128;
    const uint32_t sb0 = smem_u32(sm);
    const int hc = h * HD;

    #pragma unroll
    for (int it = 0; it < 4; it++) {
        int idx = tid + it * 256;
        int row = idx >> 3, seg = idx & 7;
        cpa16(sb0 + (uint32_t)(row * GP + seg * 8) * 2,
              Qh + (size_t)(q0 + row) * DIM + hc + seg * 8);
    }
    CP_COMMIT(); CP_WAIT0();
    __syncthreads();

    uint32_t qh[4][4];
    #pragma unroll
    for (int ks = 0; ks < 4; ks++) {
        uint32_t a = sb0 + (uint32_t)((wid * 16 + (lane & 15)) * GP
                                      + ks * 16 + (lane >> 4) * 8) * 2;
        ldm_x4(a, qh[ks]);
    }
    __syncthreads();

    auto load_kv = [&](int s, int k0) {
        uint32_t base = sb0 + (uint32_t)s * A_STAGE * 2;
        #pragma unroll
        for (int t = 0; t < 2; t++) {
            const __half* src = (t == 0) ? Kh : Vh;
            #pragma unroll
            for (int it = 0; it < 2; it++) {
                int id2 = tid + it * 256;
                int row = id2 >> 3, seg = id2 & 7;
                cpa16(base + (uint32_t)(t * A_T + row * GP + seg * 8) * 2,
                      src + (size_t)(k0 + row) * DIM + hc + seg * 8);
            }
        }
        CP_COMMIT();
    };

    float m_i[2] = {-1e30f, -1e30f}, l_i[2] = {0.f, 0.f};
    float O[8][4];
    #pragma unroll
    for (int d = 0; d < 8; d++)
        #pragma unroll
        for (int c = 0; c < 4; c++) O[d][c] = 0.f;

    load_kv(0, 0);
    for (int kt = 0; kt < LTOT / 64; kt++) {
        if (kt + 1 < LTOT / 64) { load_kv((kt + 1) & 1, (kt + 1) * 64); CP_WAIT1(); }
        else CP_WAIT0();
        __syncthreads();
        uint32_t kb = sb0 + (uint32_t)(kt & 1) * A_STAGE * 2;

        float S[8][4];
        #pragma unroll
        for (int nt = 0; nt < 8; nt++)
            #pragma unroll
            for (int c = 0; c < 4; c++) S[nt][c] = 0.f;

        #pragma unroll
        for (int ks = 0; ks < 4; ks++)
            #pragma unroll
            for (int nt = 0; nt < 8; nt++) {
                uint32_t bh[2];
                uint32_t b = kb + (uint32_t)((nt * 8 + (lane & 7)) * GP
                                             + ks * 16 + ((lane >> 3) & 1) * 8) * 2;
                ldm_x2(b, bh);
                mma16816(S[nt], qh[ks], bh);
            }

        uint32_t pa[4][4];
        #pragma unroll
        for (int hf = 0; hf < 2; hf++) {
            float tm = -1e30f;
            #pragma unroll
            for (int nt = 0; nt < 8; nt++)
                #pragma unroll
                for (int j = 0; j < 2; j++) {
                    S[nt][hf * 2 + j] *= 0.125f;
                    tm = fmaxf(tm, S[nt][hf * 2 + j]);
                }
            tm = fmaxf(tm, __shfl_xor_sync(0xffffffffu, tm, 1));
            tm = fmaxf(tm, __shfl_xor_sync(0xffffffffu, tm, 2));
            float mnew = fmaxf(m_i[hf], tm);
            float alpha = __expf(m_i[hf] - mnew);
            float rs = 0.f;
            #pragma unroll
            for (int nt = 0; nt < 8; nt++)
                #pragma unroll
                for (int j = 0; j < 2; j++) {
                    float p = __expf(S[nt][hf * 2 + j] - mnew);
                    S[nt][hf * 2 + j] = p;
                    rs += p;
                }
            rs += __shfl_xor_sync(0xffffffffu, rs, 1);
            rs += __shfl_xor_sync(0xffffffffu, rs, 2);
            l_i[hf] = l_i[hf] * alpha + rs;
            m_i[hf] = mnew;
            #pragma unroll
            for (int d = 0; d < 8; d++)
                #pragma unroll
                for (int j = 0; j < 2; j++) O[d][hf * 2 + j] *= alpha;
        }
        #pragma unroll
        for (int ks = 0; ks < 4; ks++) {
            __half2 p0 = __floats2half2_rn(S[2 * ks][0], S[2 * ks][1]);
            __half2 p1 = __floats2half2_rn(S[2 * ks][2], S[2 * ks][3]);
            __half2 p2 = __floats2half2_rn(S[2 * ks + 1][0], S[2 * ks + 1][1]);
            __half2 p3 = __floats2half2_rn(S[2 * ks + 1][2], S[2 * ks + 1][3]);
            pa[ks][0] = *(uint32_t*)&p0; pa[ks][1] = *(uint32_t*)&p1;
            pa[ks][2] = *(uint32_t*)&p2; pa[ks][3] = *(uint32_t*)&p3;
        }

        #pragma unroll
        for (int ks = 0; ks < 4; ks++)
            #pragma unroll
            for (int dt = 0; dt < 8; dt++) {
                uint32_t bh[2];
                uint32_t b = kb + (uint32_t)(A_T + (ks * 16 + (lane & 15)) * GP
                                             + dt * 8) * 2;
                ldm_x2t(b, bh);
                mma16816(O[dt], pa[ks], bh);
            }
        __syncthreads();
    }

    #pragma unroll
    for (int hf = 0; hf < 2; hf++) {
        float inv = 1.f / l_i[hf];
        int row = q0 + wid * 16 + (lane >> 2) + hf * 8;
        #pragma unroll
        for (int dt = 0; dt < 8; dt++) {
            float v0 = O[dt][hf * 2] * inv, v1 = O[dt][hf * 2 + 1] * inv;
            int col = hc + dt * 8 + (lane & 3) * 2;
            __half h0 = __float2half_rn(v0), h1 = __float2half_rn(v1);
            *(__half2*)(Oh + (size_t)row * DIM + col) = __halves2half2(h0, h1);
            *(__half2*)(Ol + (size_t)row * DIM + col) = __halves2half2(
                __float2half_rn(v0 - __half2float(h0)),
                __float2half_rn(v1 - __half2float(h1)));
        }
    }
}

// ---------------------------------------------------------------------------
// Launch
// ---------------------------------------------------------------------------
extern "C" void kernel_launch(void* const* d_in, const int* in_sizes, int n_in,
                              void* d_out, int out_size)
{
    const float* hs  = (const float*)d_in[0];
    const float* ehs = (const float*)d_in[1];
    const float* Wq  = (const float*)d_in[2];
    const float* bq  = (const float*)d_in[3];
    const float* Wk  = (const float*)d_in[4];
    const float* bk  = (const float*)d_in[5];
    const float* Wv  = (const float*)d_in[6];
    const float* bv  = (const float*)d_in[7];
    const float* Waq = (const float*)d_in[8];
    const float* baq = (const float*)d_in[9];
    const float* Wak = (const float*)d_in[10];
    const float* bak = (const float*)d_in[11];
    const float* Wav = (const float*)d_in[12];
    const float* bav = (const float*)d_in[13];
    const float* Wo  = (const float*)d_in[14];
    const float* bo  = (const float*)d_in[15];
    const float* Wao = (const float*)d_in[16];
    const float* bao = (const float*)d_in[17];
    const float* gq  = (const float*)d_in[18];
    const float* gk  = (const float*)d_in[19];
    const float* gaq = (const float*)d_in[20];
    const float* gak = (const float*)d_in[21];
    float* out = (float*)d_out;

    __half *hshi, *ehi, *whi, *qhi, *khi, *vhi, *ohi, *olo;
    cudaGetSymbolAddress((void**)&hshi, g_hshi);
    cudaGetSymbolAddress((void**)&ehi, g_ehi);
    cudaGetSymbolAddress((void**)&whi, g_whi);
    cudaGetSymbolAddress((void**)&qhi, g_qhi);
    cudaGetSymbolAddress((void**)&khi, g_khi);
    cudaGetSymbolAddress((void**)&vhi, g_vhi);
    cudaGetSymbolAddress((void**)&ohi, g_ohi);
    cudaGetSymbolAddress((void**)&olo, g_olo);

    const float* Ws[8] = {Wq, Wk, Wv, Waq, Wak, Wav, Wo, Wao};
    __half* wh[8];
    W8 wc;
    for (int i = 0; i < 8; i++) {
        wh[i] = whi + (size_t)i * DIM * DIM;
        wc.s[i] = Ws[i];
        wc.d[i] = wh[i];
    }
    cvt_hi8<<<dim3(DIM * DIM / 8 / 256, 8), 256>>>(wc);
    cvt_hi<<<(S_IMG * DIM / 8 + 255) / 256, 256>>>(hs, hshi, S_IMG * DIM);
    cvt_hi<<<(T_TXT * DIM / 8 + 255) / 256, 256>>>(ehs, ehi, T_TXT * DIM);

    cudaFuncSetAttribute(gemm_split<false>, cudaFuncAttributeMaxDynamicSharedMemorySize, GEMM_SMEM_HI);
    cudaFuncSetAttribute(gemm_split<true>,  cudaFuncAttributeMaxDynamicSharedMemorySize, GEMM_SMEM_LO);
    cudaFuncSetAttribute(attn_mma, cudaFuncAttributeMaxDynamicSharedMemorySize, ATT_SMEM);

    // Projections (X hi-only): z = {q,k,v}; hi-only outputs
    GArg pa;
    pa.Ahi[0] = hshi; pa.Alo[0] = nullptr; pa.Ahi[1] = ehi; pa.Alo[1] = nullptr;
    pa.Whi[0][0] = wh[0]; pa.Whi[0][1] = wh[1]; pa.Whi[0][2] = wh[2];
    pa.Whi[1][0] = wh[3]; pa.Whi[1][1] = wh[4]; pa.Whi[1][2] = wh[5];
    pa.bias[0][0] = bq;  pa.bias[0][1] = bk;  pa.bias[0][2] = bv;
    pa.bias[1][0] = baq; pa.bias[1][1] = bak; pa.bias[1][2] = bav;
    pa.gamma[0][0] = gq;  pa.gamma[0][1] = gk;  pa.gamma[0][2] = nullptr;
    pa.gamma[1][0] = gaq; pa.gamma[1][1] = gak; pa.gamma[1][2] = nullptr;
    pa.Ohi[0] = qhi; pa.Ohi[1] = khi; pa.Ohi[2] = vhi;
    pa.Olo[0] = nullptr; pa.Olo[1] = nullptr; pa.Olo[2] = nullptr;
    pa.Of[0] = pa.Of[1] = pa.Of[2] = nullptr;
    gemm_split<false><<<dim3(DIM / 128, LTOT / 128, 3), 256, GEMM_SMEM_HI>>>(pa);

    attn_mma<<<dim3(LTOT / 128, NH), 256, ATT_SMEM>>>(qhi, khi, vhi, ohi, olo);

    // Output projection (O hi+lo, 2-term) straight into d_out
    GArg po;
    po.Ahi[0] = ohi; po.Alo[0] = olo;
    po.Ahi[1] = ohi + (size_t)S_IMG * DIM; po.Alo[1] = olo + (size_t)S_IMG * DIM;
    po.Whi[0][0] = wh[6]; po.Whi[1][0] = wh[7];
    po.Whi[0][1] = po.Whi[0][2] = po.Whi[1][1] = po.Whi[1][2] = nullptr;
    po.bias[0][0] = bo; po.bias[1][0] = bao;
    po.bias[0][1] = po.bias[0][2] = po.bias[1][1] = po.bias[1][2] = nullptr;
    po.gamma[0][0] = po.gamma[0][1] = po.gamma[0][2] = nullptr;
    po.gamma[1][0] = po.gamma[1][1] = po.gamma[1][2] = nullptr;
    po.Ohi[0] = po.Ohi[1] = po.Ohi[2] = nullptr;
    po.Olo[0] = po.Olo[1] = po.Olo[2] = nullptr;
    po.Of[0] = out; po.Of[1] = po.Of[2] = nullptr;
    gemm_split<true><<<dim3(DIM / 128, LTOT / 128, 1), 256, GEMM_SMEM_LO>>>(po);
}

// round 17
// speedup vs baseline: 2.0894x; 1.1561x over previous
#include <cuda_runtime.h>
#include <cuda_fp16.h>
#include <cstdint>

#define DIM   1536
#define NH    24
#define HD    64
#define S_IMG 2048
#define T_TXT 512
#define LTOT  2560
#define GP    72

// ---------------- device scratch (no allocation allowed) -------------------
__device__ __half g_hshi[S_IMG * DIM];
__device__ __half g_ehi[T_TXT * DIM];
__device__ __half g_whi[8][DIM * DIM];
__device__ __half g_qhi[LTOT * DIM];
__device__ __half g_khi[LTOT * DIM];
__device__ __half g_vhi[LTOT * DIM];
__device__ __half g_ohi[LTOT * DIM];

// ---------------- base-ISA PTX helpers -------------------------------------
__device__ __forceinline__ uint32_t smem_u32(const void* p) {
    uint32_t a;
    asm("{ .reg .u64 t; cvta.to.shared.u64 t, %1; cvt.u32.u64 %0, t; }" : "=r"(a) : "l"(p));
    return a;
}
__device__ __forceinline__ void ldm_x4(uint32_t a, uint32_t* r) {
    asm volatile("ldmatrix.sync.aligned.m8n8.x4.shared.b16 {%0,%1,%2,%3}, [%4];"
        : "=r"(r[0]), "=r"(r[1]), "=r"(r[2]), "=r"(r[3]) : "r"(a));
}
__device__ __forceinline__ void ldm_x2(uint32_t a, uint32_t* r) {
    asm volatile("ldmatrix.sync.aligned.m8n8.x2.shared.b16 {%0,%1}, [%2];"
        : "=r"(r[0]), "=r"(r[1]) : "r"(a));
}
__device__ __forceinline__ void ldm_x2t(uint32_t a, uint32_t* r) {
    asm volatile("ldmatrix.sync.aligned.m8n8.x2.trans.shared.b16 {%0,%1}, [%2];"
        : "=r"(r[0]), "=r"(r[1]) : "r"(a));
}
__device__ __forceinline__ void mma16816(float* c, const uint32_t* a, const uint32_t* b) {
    asm volatile(
        "mma.sync.aligned.m16n8k16.row.col.f32.f16.f16.f32 "
        "{%0,%1,%2,%3}, {%4,%5,%6,%7}, {%8,%9}, {%0,%1,%2,%3};"
        : "+f"(c[0]), "+f"(c[1]), "+f"(c[2]), "+f"(c[3])
        : "r"(a[0]), "r"(a[1]), "r"(a[2]), "r"(a[3]), "r"(b[0]), "r"(b[1]));
}
__device__ __forceinline__ uint32_t ex2_h2(uint32_t u) {
    asm("ex2.approx.f16x2 %0, %0;" : "+r"(u));
    return u;
}
__device__ __forceinline__ void cpa16(uint32_t d, const void* g) {
    asm volatile("cp.async.cg.shared.global [%0], [%1], 16;" :: "r"(d), "l"(g));
}
#define CP_COMMIT() asm volatile("cp.async.commit_group;" ::: "memory")
#define CP_WAIT1()  asm volatile("cp.async.wait_group 1;" ::: "memory")
#define CP_WAIT0()  asm volatile("cp.async.wait_group 0;" ::: "memory")

// ---------------------------------------------------------------------------
// Converts
// ---------------------------------------------------------------------------
struct W8 { const float* s[8]; __half* d[8]; };

__global__ __launch_bounds__(256) void cvt_hi8(W8 w) {
    const float* s = w.s[blockIdx.y];
    __half* d = w.d[blockIdx.y];
    int i = (blockIdx.x * 256 + threadIdx.x) * 8;
    float4 a = *(const float4*)(s + i);
    float4 b = *(const float4*)(s + i + 4);
    __half2 h[4];
    h[0] = __floats2half2_rn(a.x, a.y);
    h[1] = __floats2half2_rn(a.z, a.w);
    h[2] = __floats2half2_rn(b.x, b.y);
    h[3] = __floats2half2_rn(b.z, b.w);
    *(uint4*)(d + i) = *(uint4*)h;
}

__global__ __launch_bounds__(256) void cvt_hi(
    const float* __restrict__ s, __half* __restrict__ d, int n)
{
    int i = (blockIdx.x * 256 + threadIdx.x) * 8;
    if (i >= n) return;
    float4 a = *(const float4*)(s + i);
    float4 b = *(const float4*)(s + i + 4);
    __half2 h[4];
    h[0] = __floats2half2_rn(a.x, a.y);
    h[1] = __floats2half2_rn(a.z, a.w);
    h[2] = __floats2half2_rn(b.x, b.y);
    h[3] = __floats2half2_rn(b.z, b.w);
    *(uint4*)(d + i) = *(uint4*)h;
}

// ---------------------------------------------------------------------------
// GEMM: Y = A @ Wh^T + b (+ optional fused per-head LN). A hi-only.
// 128x128 tile, BK=64, cp.async double-buffered, 8 warps 4(M)x2(N), x2 B-loads.
// ---------------------------------------------------------------------------
struct GArg {
    const __half* Ahi[2];
    const __half* Whi[2][3];
    const float* bias[2][3]; const float* gamma[2][3];
    __half* Ohi[3]; float* Of[3];
};

#define G_T (128 * GP)
#define GEMM_SMEM (2 * 2 * G_T * 2)

__global__ __launch_bounds__(256, 2) void gemm_hi(GArg g)
{
    extern __shared__ __half sm[];
    const int tid = threadIdx.x, wid = tid >> 5, lane = tid & 31;
    const int part = blockIdx.y >= 16;
    const int arow0 = (part ? blockIdx.y - 16 : blockIdx.y) * 128;
    const int mOut = blockIdx.y * 128;
    const int z = blockIdx.z;
    const int n0 = blockIdx.x * 128;
    const __half* Ah = g.Ahi[part];
    const __half* Wh = g.Whi[part][z];
    const uint32_t sb0 = smem_u32(sm);

    auto load_stage = [&](int s, int k0) {
        uint32_t base = sb0 + (uint32_t)s * (2 * G_T) * 2;
        #pragma unroll
        for (int t = 0; t < 2; t++) {
            const __half* src = t ? Wh : Ah;
            const int rb = t ? n0 : arow0;
            #pragma unroll
            for (int it = 0; it < 4; it++) {
                int idx = tid + it * 256;
                int row = idx >> 3, seg = idx & 7;
                cpa16(base + (uint32_t)(t * G_T + row * GP + seg * 8) * 2,
                      src + (size_t)(rb + row) * DIM + k0 + seg * 8);
            }
        }
        CP_COMMIT();
    };

    float C[2][8][4];
    #pragma unroll
    for (int a = 0; a < 2; a++)
        #pragma unroll
        for (int b = 0; b < 8; b++)
            #pragma unroll
            for (int c = 0; c < 4; c++) C[a][b][c] = 0.f;

    const int wm = (wid & 3) * 32;
    const int wn = (wid >> 2) * 64;

    load_stage(0, 0);
    for (int kc = 0; kc < 24; kc++) {
        if (kc + 1 < 24) { load_stage((kc + 1) & 1, (kc + 1) * 64); CP_WAIT1(); }
        else CP_WAIT0();
        __syncthreads();
        uint32_t sb = sb0 + (uint32_t)(kc & 1) * (2 * G_T) * 2;
        #pragma unroll
        for (int ks = 0; ks < 4; ks++) {
            uint32_t ah[2][4];
            #pragma unroll
            for (int mt = 0; mt < 2; mt++) {
                uint32_t a = sb + (uint32_t)((wm + mt * 16 + (lane & 15)) * GP
                                             + ks * 16 + (lane >> 4) * 8) * 2;
                ldm_x4(a, ah[mt]);
            }
            #pragma unroll
            for (int nt = 0; nt < 8; nt++) {
                uint32_t bh[2];
                uint32_t b = sb + (uint32_t)(G_T + (wn + nt * 8 + (lane & 7)) * GP
                                             + ks * 16 + ((lane >> 3) & 1) * 8) * 2;
                ldm_x2(b, bh);
                #pragma unroll
                for (int mt = 0; mt < 2; mt++)
                    mma16816(C[mt][nt], ah[mt], bh);
            }
        }
        __syncthreads();
    }

    const float* bias = g.bias[part][z];
    const float* gam  = g.gamma[part][z];
    __half* Oh = g.Ohi[z]; float* Of = g.Of[z];

    #pragma unroll
    for (int mt = 0; mt < 2; mt++)
        #pragma unroll
        for (int hf = 0; hf < 2; hf++) {
            const int row = mOut + wm + mt * 16 + (lane >> 2) + hf * 8;
            float v[16];
            #pragma unroll
            for (int nt = 0; nt < 8; nt++)
                #pragma unroll
                for (int j = 0; j < 2; j++)
                    v[nt * 2 + j] = C[mt][nt][hf * 2 + j]
                                  + bias[n0 + wn + nt * 8 + (lane & 3) * 2 + j];
            if (gam) {
                float s1 = 0.f, s2 = 0.f;
                #pragma unroll
                for (int c = 0; c < 16; c++) { s1 += v[c]; s2 += v[c] * v[c]; }
                s1 += __shfl_xor_sync(0xffffffffu, s1, 1);
                s2 += __shfl_xor_sync(0xffffffffu, s2, 1);
                s1 += __shfl_xor_sync(0xffffffffu, s1, 2);
                s2 += __shfl_xor_sync(0xffffffffu, s2, 2);
                float mean = s1 * (1.f / 64);
                float var = s2 * (1.f / 64) - mean * mean;
                float inv = rsqrtf(var + 1e-5f);
                #pragma unroll
                for (int nt = 0; nt < 8; nt++)
                    #pragma unroll
                    for (int j = 0; j < 2; j++) {
                        int c = nt * 2 + j;
                        v[c] = (v[c] - mean) * inv * gam[nt * 8 + (lane & 3) * 2 + j];
                    }
            }
            if (Oh) {
                #pragma unroll
                for (int nt = 0; nt < 8; nt++) {
                    int col = n0 + wn + nt * 8 + (lane & 3) * 2;
                    *(__half2*)(Oh + (size_t)row * DIM + col) =
                        __floats2half2_rn(v[nt * 2], v[nt * 2 + 1]);
                }
            } else {
                #pragma unroll
                for (int nt = 0; nt < 8; nt++) {
                    int col = n0 + wn + nt * 8 + (lane & 3) * 2;
                    *(float2*)(Of + (size_t)row * DIM + col) =
                        make_float2(v[nt * 2], v[nt * 2 + 1]);
                }
            }
        }
}

// ---------------------------------------------------------------------------
// mma flash attention. 8 warps x 16 q-rows, K-tiles of 64. S = Qh @ Kh.
// Softmax in log2 domain: ex2.approx.f16x2 on packed half2; row-sum l via
// a ones-column mma (L accumulator, alpha-rescaled like O).
// ---------------------------------------------------------------------------
#define A_T (64 * GP)
#define A_STAGE (2 * A_T)
#define ATT_SMEM (2 * A_STAGE * 2)
#define SCALE2 0.1803368801111204f   /* 0.125 * log2(e) */

__global__ __launch_bounds__(256, 2) void attn_mma(
    const __half* __restrict__ Qh, const __half* __restrict__ Kh,
    const __half* __restrict__ Vh, __half* __restrict__ Oh)
{
    extern __shared__ __half sm[];
    const int tid = threadIdx.x, wid = tid >> 5, lane = tid & 31;
    const int h = blockIdx.y;
    const int q0 = blockIdx.x * 128;
    const uint32_t sb0 = smem_u32(sm);
    const int hc = h * HD;
    const uint32_t ONES = 0x3C003C00u;
    const uint32_t bones[2] = {ONES, ONES};

    #pragma unroll
    for (int it = 0; it < 4; it++) {
        int idx = tid + it * 256;
        int row = idx >> 3, seg = idx & 7;
        cpa16(sb0 + (uint32_t)(row * GP + seg * 8) * 2,
              Qh + (size_t)(q0 + row) * DIM + hc + seg * 8);
    }
    CP_COMMIT(); CP_WAIT0();
    __syncthreads();

    uint32_t qh[4][4];
    #pragma unroll
    for (int ks = 0; ks < 4; ks++) {
        uint32_t a = sb0 + (uint32_t)((wid * 16 + (lane & 15)) * GP
                                      + ks * 16 + (lane >> 4) * 8) * 2;
        ldm_x4(a, qh[ks]);
    }
    __syncthreads();

    auto load_kv = [&](int s, int k0) {
        uint32_t base = sb0 + (uint32_t)s * A_STAGE * 2;
        #pragma unroll
        for (int t = 0; t < 2; t++) {
            const __half* src = (t == 0) ? Kh : Vh;
            #pragma unroll
            for (int it = 0; it < 2; it++) {
                int id2 = tid + it * 256;
                int row = id2 >> 3, seg = id2 & 7;
                cpa16(base + (uint32_t)(t * A_T + row * GP + seg * 8) * 2,
                      src + (size_t)(k0 + row) * DIM + hc + seg * 8);
            }
        }
        CP_COMMIT();
    };

    float m_i[2] = {-1e30f, -1e30f};
    float O[8][4], L[4];
    #pragma unroll
    for (int d = 0; d < 8; d++)
        #pragma unroll
        for (int c = 0; c < 4; c++) O[d][c] = 0.f;
    #pragma unroll
    for (int c = 0; c < 4; c++) L[c] = 0.f;

    load_kv(0, 0);
    for (int kt = 0; kt < LTOT / 64; kt++) {
        if (kt + 1 < LTOT / 64) { load_kv((kt + 1) & 1, (kt + 1) * 64); CP_WAIT1(); }
        else CP_WAIT0();
        __syncthreads();
        uint32_t kb = sb0 + (uint32_t)(kt & 1) * A_STAGE * 2;

        float S[8][4];
        #pragma unroll
        for (int nt = 0; nt < 8; nt++)
            #pragma unroll
            for (int c = 0; c < 4; c++) S[nt][c] = 0.f;

        #pragma unroll
        for (int ks = 0; ks < 4; ks++)
            #pragma unroll
            for (int nt = 0; nt < 8; nt++) {
                uint32_t bh[2];
                uint32_t b = kb + (uint32_t)((nt * 8 + (lane & 7)) * GP
                                             + ks * 16 + ((lane >> 3) & 1) * 8) * 2;
                ldm_x2(b, bh);
                mma16816(S[nt], qh[ks], bh);
            }

        // log2-domain online softmax
        #pragma unroll
        for (int hf = 0; hf < 2; hf++) {
            float tm = -1e30f;
            #pragma unroll
            for (int nt = 0; nt < 8; nt++)
                #pragma unroll
                for (int j = 0; j < 2; j++) {
                    S[nt][hf * 2 + j] *= SCALE2;
                    tm = fmaxf(tm, S[nt][hf * 2 + j]);
                }
            tm = fmaxf(tm, __shfl_xor_sync(0xffffffffu, tm, 1));
            tm = fmaxf(tm, __shfl_xor_sync(0xffffffffu, tm, 2));
            float mnew = fmaxf(m_i[hf], tm);
            float alpha = exp2f(m_i[hf] - mnew);
            m_i[hf] = mnew;
            #pragma unroll
            for (int d = 0; d < 8; d++)
                #pragma unroll
                for (int j = 0; j < 2; j++) O[d][hf * 2 + j] *= alpha;
            L[hf * 2] *= alpha;
            L[hf * 2 + 1] *= alpha;
        }

        // P = exp2(S - m) via half2 MUFU; pa packing matches mma A-layout
        uint32_t pa[4][4];
        #pragma unroll
        for (int ks = 0; ks < 4; ks++)
            #pragma unroll
            for (int r = 0; r < 4; r++) {
                int nt = 2 * ks + (r >> 1);
                int hf = r & 1;
                __half2 hv = __floats2half2_rn(S[nt][hf * 2] - m_i[hf],
                                               S[nt][hf * 2 + 1] - m_i[hf]);
                pa[ks][r] = ex2_h2(*(uint32_t*)&hv);
            }

        // O += P @ Vh ; L += P @ 1
        #pragma unroll
        for (int ks = 0; ks < 4; ks++) {
            #pragma unroll
            for (int dt = 0; dt < 8; dt++) {
                uint32_t bh[2];
                uint32_t b = kb + (uint32_t)(A_T + (ks * 16 + (lane & 15)) * GP
                                             + dt * 8) * 2;
                ldm_x2t(b, bh);
                mma16816(O[dt], pa[ks], bh);
            }
            mma16816(L, pa[ks], bones);
        }
        __syncthreads();
    }

    #pragma unroll
    for (int hf = 0; hf < 2; hf++) {
        float inv = 1.f / L[hf * 2];
        int row = q0 + wid * 16 + (lane >> 2) + hf * 8;
        #pragma unroll
        for (int dt = 0; dt < 8; dt++) {
            int col = hc + dt * 8 + (lane & 3) * 2;
            *(__half2*)(Oh + (size_t)row * DIM + col) =
                __floats2half2_rn(O[dt][hf * 2] * inv, O[dt][hf * 2 + 1] * inv);
        }
    }
}

// ---------------------------------------------------------------------------
// Launch
// ---------------------------------------------------------------------------
extern "C" void kernel_launch(void* const* d_in, const int* in_sizes, int n_in,
                              void* d_out, int out_size)
{
    const float* hs  = (const float*)d_in[0];
    const float* ehs = (const float*)d_in[1];
    const float* Wq  = (const float*)d_in[2];
    const float* bq  = (const float*)d_in[3];
    const float* Wk  = (const float*)d_in[4];
    const float* bk  = (const float*)d_in[5];
    const float* Wv  = (const float*)d_in[6];
    const float* bv  = (const float*)d_in[7];
    const float* Waq = (const float*)d_in[8];
    const float* baq = (const float*)d_in[9];
    const float* Wak = (const float*)d_in[10];
    const float* bak = (const float*)d_in[11];
    const float* Wav = (const float*)d_in[12];
    const float* bav = (const float*)d_in[13];
    const float* Wo  = (const float*)d_in[14];
    const float* bo  = (const float*)d_in[15];
    const float* Wao = (const float*)d_in[16];
    const float* bao = (const float*)d_in[17];
    const float* gq  = (const float*)d_in[18];
    const float* gk  = (const float*)d_in[19];
    const float* gaq = (const float*)d_in[20];
    const float* gak = (const float*)d_in[21];
    float* out = (float*)d_out;

    __half *hshi, *ehi, *whi, *qhi, *khi, *vhi, *ohi;
    cudaGetSymbolAddress((void**)&hshi, g_hshi);
    cudaGetSymbolAddress((void**)&ehi, g_ehi);
    cudaGetSymbolAddress((void**)&whi, g_whi);
    cudaGetSymbolAddress((void**)&qhi, g_qhi);
    cudaGetSymbolAddress((void**)&khi, g_khi);
    cudaGetSymbolAddress((void**)&vhi, g_vhi);
    cudaGetSymbolAddress((void**)&ohi, g_ohi);

    const float* Ws[8] = {Wq, Wk, Wv, Waq, Wak, Wav, Wo, Wao};
    __half* wh[8];
    W8 wc;
    for (int i = 0; i < 8; i++) {
        wh[i] = whi + (size_t)i * DIM * DIM;
        wc.s[i] = Ws[i];
        wc.d[i] = wh[i];
    }
    cvt_hi8<<<dim3(DIM * DIM / 8 / 256, 8), 256>>>(wc);
    cvt_hi<<<(S_IMG * DIM / 8 + 255) / 256, 256>>>(hs, hshi, S_IMG * DIM);
    cvt_hi<<<(T_TXT * DIM / 8 + 255) / 256, 256>>>(ehs, ehi, T_TXT * DIM);

    cudaFuncSetAttribute(gemm_hi, cudaFuncAttributeMaxDynamicSharedMemorySize, GEMM_SMEM);
    cudaFuncSetAttribute(attn_mma, cudaFuncAttributeMaxDynamicSharedMemorySize, ATT_SMEM);

    // Projections: z = {q,k,v}
    GArg pa;
    pa.Ahi[0] = hshi; pa.Ahi[1] = ehi;
    pa.Whi[0][0] = wh[0]; pa.Whi[0][1] = wh[1]; pa.Whi[0][2] = wh[2];
    pa.Whi[1][0] = wh[3]; pa.Whi[1][1] = wh[4]; pa.Whi[1][2] = wh[5];
    pa.bias[0][0] = bq;  pa.bias[0][1] = bk;  pa.bias[0][2] = bv;
    pa.bias[1][0] = baq; pa.bias[1][1] = bak; pa.bias[1][2] = bav;
    pa.gamma[0][0] = gq;  pa.gamma[0][1] = gk;  pa.gamma[0][2] = nullptr;
    pa.gamma[1][0] = gaq; pa.gamma[1][1] = gak; pa.gamma[1][2] = nullptr;
    pa.Ohi[0] = qhi; pa.Ohi[1] = khi; pa.Ohi[2] = vhi;
    pa.Of[0] = pa.Of[1] = pa.Of[2] = nullptr;
    gemm_hi<<<dim3(DIM / 128, LTOT / 128, 3), 256, GEMM_SMEM>>>(pa);

    attn_mma<<<dim3(LTOT / 128, NH), 256, ATT_SMEM>>>(qhi, khi, vhi, ohi);

    // Output projection (O hi-only) straight into d_out
    GArg po;
    po.Ahi[0] = ohi; po.Ahi[1] = ohi + (size_t)S_IMG * DIM;
    po.Whi[0][0] = wh[6]; po.Whi[1][0] = wh[7];
    po.Whi[0][1] = po.Whi[0][2] = po.Whi[1][1] = po.Whi[1][2] = nullptr;
    po.bias[0][0] = bo; po.bias[1][0] = bao;
    po.bias[0][1] = po.bias[0][2] = po.bias[1][1] = po.bias[1][2] = nullptr;
    po.gamma[0][0] = po.gamma[0][1] = po.gamma[0][2] = nullptr;
    po.gamma[1][0] = po.gamma[1][1] = po.gamma[1][2] = nullptr;
    po.Ohi[0] = po.Ohi[1] = po.Ohi[2] = nullptr;
    po.Of[0] = out; po.Of[1] = po.Of[2] = nullptr;
    gemm_hi<<<dim3(DIM / 128, LTOT / 128, 1), 256, GEMM_SMEM>>>(po);
}